// round 13
// baseline (speedup 1.0000x reference)
#include <cuda_runtime.h>
#include <cuda_fp16.h>
#include <math.h>
#include <stdint.h>

#define NB  4
#define TI  512
#define TO  64
#define TO1 65
#define VV  1024
#define EE  512
#define HH  512
#define JJ  512
#define G4  2048
#define M_SEQ (NB*TO1)           // 260
#define M_OUT (NB*TI*TO1)        // 133120
#define NTICK (TO1 + 2)
#define GRID_LSTM 96
#define WSM_BYTES (64*512*4)     // per-block Whh slice in dynamic SMEM (128 KB)

// Scratch (device globals -- no allocation allowed)
__device__ float g_xa[M_SEQ*EE];
__device__ float g_xb[M_SEQ*HH];
__device__ float g_xg[M_SEQ*G4];
__device__ float g_encp[NB*TI*JJ];
__device__ float g_decp[M_SEQ*JJ];
__device__ float g_h[3][2][NB*HH];
__device__ unsigned g_done[3];         // per-layer tick arrival counters
__device__ unsigned g_T[M_OUT*256];    // fp16 tanh(enc+dec), fragment-packed (136 MB)
__device__ unsigned g_bw[VV*256];      // fp16 out_w, fragment-packed (1 MB)

// ---------------------------------------------------------------------------
__global__ void k_embed(const int* __restrict__ tgt, const float* __restrict__ emb,
                        float* __restrict__ x) {
    int idx = blockIdx.x*blockDim.x + threadIdx.x;
    if (idx < 3) g_done[idx] = 0u;
    if (idx >= M_SEQ*EE) return;
    int e = idx & (EE-1);
    int m = idx >> 9;
    int n = m / TO1, t = m - n*TO1;
    int tok = (t == 0) ? 0 : tgt[n*TO + t - 1];
    x[idx] = emb[tok*EE + e];
}

// ---------------------------------------------------------------------------
// C[m,n] = sum_k A[m,k]*B[n,k] + b1[n] + b2[n], register-prefetch double-buffer
// ---------------------------------------------------------------------------
__global__ void k_gemm_abT(const float* __restrict__ A, const float* __restrict__ B,
                           const float* __restrict__ b1, const float* __restrict__ b2,
                           float* __restrict__ C, int M, int Nn, int K) {
    __shared__ float As[16][64];
    __shared__ float Bs[16][64];
    const int tid = threadIdx.x;
    const int m0 = blockIdx.x*64, n0 = blockIdx.y*64;
    const int lr = tid >> 2;
    const int lk = (tid & 3) << 2;
    const int tx = tid & 15, ty = tid >> 4;
    float acc[4][4] = {};
    const bool mval = (m0 + lr) < M;
    const float* Ap = A + (size_t)(m0+lr)*K + lk;
    const float* Bp = B + (size_t)(n0+lr)*K + lk;

    float4 av = make_float4(0.f,0.f,0.f,0.f);
    if (mval) av = *(const float4*)(Ap);
    float4 bv = *(const float4*)(Bp);

    for (int k0 = 0; k0 < K; k0 += 16) {
        As[lk+0][lr]=av.x; As[lk+1][lr]=av.y; As[lk+2][lr]=av.z; As[lk+3][lr]=av.w;
        Bs[lk+0][lr]=bv.x; Bs[lk+1][lr]=bv.y; Bs[lk+2][lr]=bv.z; Bs[lk+3][lr]=bv.w;
        __syncthreads();
        float4 av2 = make_float4(0.f,0.f,0.f,0.f);
        float4 bv2 = make_float4(0.f,0.f,0.f,0.f);
        if (k0 + 16 < K) {
            if (mval) av2 = *(const float4*)(Ap + k0 + 16);
            bv2 = *(const float4*)(Bp + k0 + 16);
        }
#pragma unroll
        for (int k = 0; k < 16; k++) {
            float4 a4 = *(const float4*)&As[k][ty*4];
            float4 b4 = *(const float4*)&Bs[k][tx*4];
            float aa[4] = {a4.x,a4.y,a4.z,a4.w};
            float bb[4] = {b4.x,b4.y,b4.z,b4.w};
#pragma unroll
            for (int i=0;i<4;i++)
#pragma unroll
                for (int j=0;j<4;j++) acc[i][j] += aa[i]*bb[j];
        }
        __syncthreads();
        av = av2; bv = bv2;
    }
    float bias[4];
#pragma unroll
    for (int j=0;j<4;j++) {
        int nn = n0 + tx*4 + j;
        bias[j] = (b1 ? b1[nn] : 0.f) + (b2 ? b2[nn] : 0.f);
    }
#pragma unroll
    for (int i=0;i<4;i++) {
        int m = m0 + ty*4 + i;
        if (m < M) {
            float4 o = make_float4(acc[i][0]+bias[0], acc[i][1]+bias[1],
                                   acc[i][2]+bias[2], acc[i][3]+bias[3]);
            *(float4*)&C[(size_t)m*Nn + n0 + tx*4] = o;
        }
    }
}

// ---------------------------------------------------------------------------
// Persistent wavefront LSTM; Whh in SMEM; packed f32x2 FMA; PER-LAYER
// dependency barriers with 1-tick skew tolerance (no global lockstep).
// ---------------------------------------------------------------------------
__device__ __forceinline__ float sigf(float x) { return 1.f/(1.f + expf(-x)); }

__device__ __forceinline__ void fma2(unsigned long long& acc,
                                     unsigned long long a, unsigned long long b) {
    asm("fma.rn.f32x2 %0, %1, %2, %0;" : "+l"(acc) : "l"(a), "l"(b));
}

__device__ __forceinline__ void dot8x2(const float* Wrow0, const float* sh,
                                       int lane, int wstride,
                                       unsigned long long acc2[8][4]) {
#pragma unroll
    for (int it = 0; it < 4; it++) {
        const int kv4 = (it*32 + lane) * 4;
        ulonglong2 H0 = *(const ulonglong2*)&sh[0*HH + kv4];
        ulonglong2 H1 = *(const ulonglong2*)&sh[1*HH + kv4];
        ulonglong2 H2 = *(const ulonglong2*)&sh[2*HH + kv4];
        ulonglong2 H3 = *(const ulonglong2*)&sh[3*HH + kv4];
#pragma unroll
        for (int r = 0; r < 8; r++) {
            ulonglong2 W = *(const ulonglong2*)(Wrow0 + r*wstride + kv4);
            fma2(acc2[r][0], W.x, H0.x); fma2(acc2[r][0], W.y, H0.y);
            fma2(acc2[r][1], W.x, H1.x); fma2(acc2[r][1], W.y, H1.y);
            fma2(acc2[r][2], W.x, H2.x); fma2(acc2[r][2], W.y, H2.y);
            fma2(acc2[r][3], W.x, H3.x); fma2(acc2[r][3], W.y, H3.y);
        }
    }
}

__device__ __forceinline__ float unpk(unsigned long long v) {
    return __uint_as_float((unsigned)(v & 0xffffffffu)) +
           __uint_as_float((unsigned)(v >> 32));
}

__device__ __forceinline__ unsigned ld_acq(unsigned* p) {
    unsigned v;
    asm volatile("ld.acquire.gpu.global.u32 %0, [%1];" : "=r"(v) : "l"(p) : "memory");
    return v;
}

__global__ void __launch_bounds__(256, 1) k_lstm_wave(
    const float* __restrict__ xg0,
    const float* __restrict__ Whh0,
    const float* __restrict__ Wih1, const float* __restrict__ Whh1,
    const float* __restrict__ bih1, const float* __restrict__ bhh1,
    const float* __restrict__ Wih2, const float* __restrict__ Whh2,
    const float* __restrict__ bih2, const float* __restrict__ bhh2,
    float* __restrict__ out_seq)
{
    extern __shared__ float Wsm[];       // [64][512] fp32 Whh slice
    const int layer = blockIdx.x >> 5;
    const int blk   = blockIdx.x & 31;
    const int j0    = blk * 16;
    const int tid   = threadIdx.x, warp = tid >> 5, lane = tid & 31;

    const float* Whh = (layer==0) ? Whh0 : (layer==1 ? Whh1 : Whh2);
    const float* Wih = (layer==1) ? Wih1 : Wih2;
    const float* bi  = (layer==1) ? bih1 : bih2;
    const float* bh  = (layer==1) ? bhh1 : bhh2;

    __shared__ __align__(16) float sh[NB*HH];
    __shared__ __align__(16) float si[NB*HH];
    __shared__ float gsm[4][NB][16];

    // Preload this block's Whh slice: local row = q*16 + jj  (q=gate)
    for (int i = tid; i < 64*512/4; i += 256) {
        int row = i >> 7;
        int k   = (i << 2) & 511;
        int q = row >> 4, jj = row & 15;
        ((float4*)Wsm)[i] = *(const float4*)&Whh[(size_t)(q*HH + j0 + jj)*HH + k];
    }

    const int rl0 = warp*8;
    const int q   = rl0 >> 4;
    const int jb  = rl0 & 15;
    const float* WsmR = Wsm + rl0*512;
    const float* WihR = Wih + (size_t)(q*HH + j0 + jb)*HH;

    const int eb = tid >> 4, ejj = tid & 15, ej = j0 + ejj;
    float c_reg = 0.f;
    float bias_q[4] = {0.f, 0.f, 0.f, 0.f};
    if (tid < 64 && layer > 0) {
#pragma unroll
        for (int qq = 0; qq < 4; qq++) bias_q[qq] = bi[qq*HH + ej] + bh[qq*HH + ej];
    }
    __syncthreads();                     // Wsm ready

    for (int tick = 0; tick < NTICK; tick++) {
        const int t = tick - layer;
        if (t >= 0 && t < TO1) {
            const int rp = (tick + 1) & 1;
            const bool havePrev = (t > 0);
            if (havePrev) {
                const float* hp = g_h[layer][rp];
                for (int i = tid; i < NB*HH; i += 256) sh[i] = __ldcg(hp + i);
            }
            if (layer > 0) {
                const float* hi = g_h[layer-1][rp];
                for (int i = tid; i < NB*HH; i += 256) si[i] = __ldcg(hi + i);
            }
            __syncthreads();

            unsigned long long acc2[8][4] = {};
            if (havePrev) dot8x2(WsmR, sh, lane, 512, acc2);
            if (layer > 0) dot8x2(WihR, si, lane, HH, acc2);

            float acc[8][4];
#pragma unroll
            for (int r = 0; r < 8; r++)
#pragma unroll
                for (int b = 0; b < 4; b++) acc[r][b] = unpk(acc2[r][b]);
#pragma unroll
            for (int r = 0; r < 8; r++) {
#pragma unroll
                for (int off = 16; off; off >>= 1) {
                    acc[r][0] += __shfl_down_sync(0xffffffffu, acc[r][0], off);
                    acc[r][1] += __shfl_down_sync(0xffffffffu, acc[r][1], off);
                    acc[r][2] += __shfl_down_sync(0xffffffffu, acc[r][2], off);
                    acc[r][3] += __shfl_down_sync(0xffffffffu, acc[r][3], off);
                }
            }
            if (lane == 0) {
#pragma unroll
                for (int r = 0; r < 8; r++) {
                    gsm[q][0][jb+r] = acc[r][0];
                    gsm[q][1][jb+r] = acc[r][1];
                    gsm[q][2][jb+r] = acc[r][2];
                    gsm[q][3][jb+r] = acc[r][3];
                }
            }
            __syncthreads();
            if (tid < 64) {
                float p[4];
                if (layer == 0) {
                    const float* xp = xg0 + (size_t)(eb*TO1 + t)*G4;
#pragma unroll
                    for (int qq = 0; qq < 4; qq++) p[qq] = gsm[qq][eb][ejj] + xp[qq*HH + ej];
                } else {
#pragma unroll
                    for (int qq = 0; qq < 4; qq++) p[qq] = gsm[qq][eb][ejj] + bias_q[qq];
                }
                float iv = sigf(p[0]), fv = sigf(p[1]), gv = tanhf(p[2]), ov = sigf(p[3]);
                c_reg = fv*c_reg + iv*gv;
                float h = ov * tanhf(c_reg);
                g_h[layer][tick & 1][eb*HH + ej] = h;
                if (layer == 2) out_seq[(size_t)(eb*TO1 + t)*HH + ej] = h;
            }
        }
        // ---- per-layer barrier: arrive for this tick, wait deps for next ----
        __syncthreads();                 // all block writes done before release
        if (tid == 0) {
            asm volatile("red.release.gpu.global.add.u32 [%0], %1;"
                         :: "l"(&g_done[layer]), "r"(1u) : "memory");
            if (tick + 1 < NTICK) {
                const unsigned tnext = 32u * (unsigned)(tick + 1);
                while (ld_acq(&g_done[layer]) < tnext) { }
                if (layer > 0)
                    while (ld_acq(&g_done[layer-1]) < tnext) { }
                if (layer < 2) {
                    const unsigned tdown = 32u * (unsigned)tick;
                    while (ld_acq(&g_done[layer+1]) < tdown) { }
                }
            }
        }
        __syncthreads();                 // broadcast acquire to whole block
    }
}

// ---------------------------------------------------------------------------
// T = fp16(tanh(encp+decp)) in m16n8k16 A-fragment order (fast HW tanh).
// ---------------------------------------------------------------------------
__device__ __forceinline__ float tanh_fast(float x) {
    float y;
    asm("tanh.approx.f32 %0, %1;" : "=f"(y) : "f"(x));
    return y;
}

__device__ __forceinline__ void row_ptrs(int m, const float* __restrict__ encp,
                                         const float* __restrict__ decp,
                                         const float*& ep, const float*& dp) {
    const int n   = m / (TI*TO1);
    const int rem = m - n*(TI*TO1);
    const int t   = rem / TO1;
    const int u   = rem - t*TO1;
    ep = encp + (size_t)(n*TI + t)*JJ;
    dp = decp + (size_t)(n*TO1 + u)*JJ;
}

__global__ void k_tanh(const float* __restrict__ encp, const float* __restrict__ decp,
                       uint4* __restrict__ T) {
    const int idx   = blockIdx.x*256 + threadIdx.x;
    const int lane  = idx & 31;
    const int ks    = (idx >> 5) & 31;
    const int mtile = idx >> 10;
    const int g = lane >> 2, tg = lane & 3;
    const int k0 = ks*16 + 2*tg;

    const float *eA, *dA, *eB, *dB;
    row_ptrs(mtile*16 + g,     encp, decp, eA, dA);
    row_ptrs(mtile*16 + g + 8, encp, decp, eB, dB);

    float2 ea0 = *(const float2*)(eA + k0), ea1 = *(const float2*)(eA + k0 + 8);
    float2 da0 = *(const float2*)(dA + k0), da1 = *(const float2*)(dA + k0 + 8);
    float2 eb0 = *(const float2*)(eB + k0), eb1 = *(const float2*)(eB + k0 + 8);
    float2 db0 = *(const float2*)(dB + k0), db1 = *(const float2*)(dB + k0 + 8);

    __half2 a0 = __floats2half2_rn(tanh_fast(ea0.x+da0.x), tanh_fast(ea0.y+da0.y));
    __half2 a1 = __floats2half2_rn(tanh_fast(eb0.x+db0.x), tanh_fast(eb0.y+db0.y));
    __half2 a2 = __floats2half2_rn(tanh_fast(ea1.x+da1.x), tanh_fast(ea1.y+da1.y));
    __half2 a3 = __floats2half2_rn(tanh_fast(eb1.x+db1.x), tanh_fast(eb1.y+db1.y));
    uint4 o;
    o.x = *(unsigned*)&a0; o.y = *(unsigned*)&a1;
    o.z = *(unsigned*)&a2; o.w = *(unsigned*)&a3;
    T[idx] = o;
}

// out_w -> fp16 in B-fragment order
__global__ void k_cvtB(const float* __restrict__ w, uint2* __restrict__ o) {
    const int idx   = blockIdx.x*256 + threadIdx.x;
    const int lane  = idx & 31;
    const int ks    = (idx >> 5) & 31;
    const int vtile = idx >> 10;
    const int g = lane >> 2, tg = lane & 3;
    const int k0 = ks*16 + 2*tg;
    const float* wp = w + (size_t)(vtile*8 + g)*JJ;
    float2 f0 = *(const float2*)(wp + k0);
    float2 f1 = *(const float2*)(wp + k0 + 8);
    __half2 b0 = __floats2half2_rn(f0.x, f0.y);
    __half2 b1 = __floats2half2_rn(f1.x, f1.y);
    uint2 v;
    v.x = *(unsigned*)&b0; v.y = *(unsigned*)&b1;
    o[idx] = v;
}

// ---------------------------------------------------------------------------
// SMEM-free fp16 HMMA GEMM with explicit 2-deep register double-buffering.
// ---------------------------------------------------------------------------
__device__ __forceinline__ void mma16816(float d[4], const unsigned a[4],
                                         const unsigned b[2]) {
    asm volatile(
        "mma.sync.aligned.m16n8k16.row.col.f32.f16.f16.f32 "
        "{%0,%1,%2,%3}, {%4,%5,%6,%7}, {%8,%9}, {%0,%1,%2,%3};"
        : "+f"(d[0]), "+f"(d[1]), "+f"(d[2]), "+f"(d[3])
        : "r"(a[0]), "r"(a[1]), "r"(a[2]), "r"(a[3]), "r"(b[0]), "r"(b[1]));
}

__global__ void __launch_bounds__(256) k_mma_out(
    const uint4* __restrict__ Tf, const uint2* __restrict__ Bf,
    float* __restrict__ out)
{
    const int tid = threadIdx.x;
    const int w = tid >> 5, lane = tid & 31;
    const int wm = w >> 2, wn = w & 3;
    const int m0 = blockIdx.x * 128;
    const int v0 = blockIdx.y * 256;

    const uint4* Ap[4];
#pragma unroll
    for (int mt = 0; mt < 4; mt++)
        Ap[mt] = Tf + ((size_t)(blockIdx.x*8 + wm*4 + mt) * 32) * 32 + lane;
    const uint2* Bp[8];
#pragma unroll
    for (int nt = 0; nt < 8; nt++)
        Bp[nt] = Bf + ((size_t)(blockIdx.y*32 + wn*8 + nt) * 32) * 32 + lane;

    float d[4][8][4];
#pragma unroll
    for (int i = 0; i < 4; i++)
#pragma unroll
        for (int j = 0; j < 8; j++)
#pragma unroll
            for (int k = 0; k < 4; k++) d[i][j][k] = 0.f;

    unsigned a[2][4][4], b[2][8][2];
#pragma unroll
    for (int mt = 0; mt < 4; mt++) {
        uint4 v = Ap[mt][0];
        a[0][mt][0] = v.x; a[0][mt][1] = v.y; a[0][mt][2] = v.z; a[0][mt][3] = v.w;
    }
#pragma unroll
    for (int nt = 0; nt < 8; nt++) {
        uint2 v = Bp[nt][0];
        b[0][nt][0] = v.x; b[0][nt][1] = v.y;
    }

#pragma unroll 2
    for (int ks = 0; ks < 32; ks++) {
        const int cur = ks & 1, nxt = cur ^ 1;
        if (ks < 31) {
#pragma unroll
            for (int mt = 0; mt < 4; mt++) {
                uint4 v = Ap[mt][(ks+1)*32];
                a[nxt][mt][0] = v.x; a[nxt][mt][1] = v.y;
                a[nxt][mt][2] = v.z; a[nxt][mt][3] = v.w;
            }
#pragma unroll
            for (int nt = 0; nt < 8; nt++) {
                uint2 v = Bp[nt][(ks+1)*32];
                b[nxt][nt][0] = v.x; b[nxt][nt][1] = v.y;
            }
        }
#pragma unroll
        for (int mt = 0; mt < 4; mt++)
#pragma unroll
            for (int nt = 0; nt < 8; nt++)
                mma16816(d[mt][nt], a[cur][mt], b[cur][nt]);
    }

    const int g = lane >> 2, tg = lane & 3;
#pragma unroll
    for (int mt = 0; mt < 4; mt++) {
        const int row = m0 + wm*64 + mt*16 + g;
#pragma unroll
        for (int nt = 0; nt < 8; nt++) {
            const int col = v0 + wn*64 + nt*8 + 2*tg;
            *(float2*)(out + (size_t)row*VV + col) =
                make_float2(d[mt][nt][0], d[mt][nt][1]);
            *(float2*)(out + (size_t)(row + 8)*VV + col) =
                make_float2(d[mt][nt][2], d[mt][nt][3]);
        }
    }
}

// ---------------------------------------------------------------------------
extern "C" void kernel_launch(void* const* d_in, const int* in_sizes, int n_in,
                              void* d_out, int out_size) {
    const float* enc_out = (const float*)d_in[0];
    const int*   tgt     = (const int*)  d_in[1];
    const float* emb     = (const float*)d_in[2];
    const float* Wih0    = (const float*)d_in[3];
    const float* Whh0    = (const float*)d_in[4];
    const float* bih0    = (const float*)d_in[5];
    const float* bhh0    = (const float*)d_in[6];
    const float* Wih1    = (const float*)d_in[7];
    const float* Whh1    = (const float*)d_in[8];
    const float* bih1    = (const float*)d_in[9];
    const float* bhh1    = (const float*)d_in[10];
    const float* Wih2    = (const float*)d_in[11];
    const float* Whh2    = (const float*)d_in[12];
    const float* bih2    = (const float*)d_in[13];
    const float* bhh2    = (const float*)d_in[14];
    const float* enc_w   = (const float*)d_in[15];
    const float* dec_w   = (const float*)d_in[16];
    const float* dec_b   = (const float*)d_in[17];
    const float* out_w   = (const float*)d_in[18];
    float* out = (float*)d_out;

    float *xa, *xb, *xg, *encp, *decp;
    unsigned *Tb, *Bw;
    cudaGetSymbolAddress((void**)&xa,   g_xa);
    cudaGetSymbolAddress((void**)&xb,   g_xb);
    cudaGetSymbolAddress((void**)&xg,   g_xg);
    cudaGetSymbolAddress((void**)&encp, g_encp);
    cudaGetSymbolAddress((void**)&decp, g_decp);
    cudaGetSymbolAddress((void**)&Tb,   g_T);
    cudaGetSymbolAddress((void**)&Bw,   g_bw);

    cudaFuncSetAttribute(k_lstm_wave, cudaFuncAttributeMaxDynamicSharedMemorySize,
                         WSM_BYTES);

    // side stream + fork/join events (created once; capture-legal fork pattern)
    static cudaStream_t s2 = nullptr;
    static cudaEvent_t evF = nullptr, evJ = nullptr;
    if (!s2) {
        cudaStreamCreateWithFlags(&s2, cudaStreamNonBlocking);
        cudaEventCreateWithFlags(&evF, cudaEventDisableTiming);
        cudaEventCreateWithFlags(&evJ, cudaEventDisableTiming);
    }

    // fork: enc_p projection runs concurrently with embed/xg/LSTM
    cudaEventRecord(evF, 0);
    cudaStreamWaitEvent(s2, evF, 0);
    {
        dim3 g((NB*TI)/64, JJ/64);
        k_gemm_abT<<<g, 256, 0, s2>>>(enc_out, enc_w, nullptr, nullptr, encp,
                                      NB*TI, JJ, 512);
    }
    cudaEventRecord(evJ, s2);

    // main stream chain
    k_embed<<<(M_SEQ*EE + 255)/256, 256>>>(tgt, emb, xa);
    k_cvtB<<<(VV/8)*32*32/256, 256>>>(out_w, (uint2*)Bw);
    {
        dim3 g((M_SEQ + 63)/64, G4/64);
        k_gemm_abT<<<g, 256>>>(xa, Wih0, bih0, bhh0, xg, M_SEQ, G4, HH);
    }
    k_lstm_wave<<<GRID_LSTM, 256, WSM_BYTES>>>(xg, Whh0,
                                    Wih1, Whh1, bih1, bhh1,
                                    Wih2, Whh2, bih2, bhh2, xb);
    {
        dim3 g((M_SEQ + 63)/64, JJ/64);
        k_gemm_abT<<<g, 256>>>(xb, dec_w, dec_b, nullptr, decp, M_SEQ, JJ, HH);
    }

    // join: tanh needs encp from s2
    cudaStreamWaitEvent(0, evJ, 0);
    k_tanh<<<(M_OUT/16)*32*32/256, 256>>>(encp, decp, (uint4*)Tb);

    {
        dim3 g(M_OUT/128, VV/256);
        k_mma_out<<<g, 256>>>((const uint4*)Tb, (const uint2*)Bw, out);
    }
}

// round 14
// speedup vs baseline: 1.0465x; 1.0465x over previous
#include <cuda_runtime.h>
#include <cuda_fp16.h>
#include <math.h>
#include <stdint.h>

#define NB  4
#define TI  512
#define TO  64
#define TO1 65
#define VV  1024
#define EE  512
#define HH  512
#define JJ  512
#define G4  2048
#define M_SEQ (NB*TO1)           // 260
#define M_OUT (NB*TI*TO1)        // 133120
#define NTICK (TO1 + 2)
#define GRID_LSTM 96
#define WSM_BYTES (64*512*4)     // per-block Whh slice in dynamic SMEM (128 KB)

// Scratch (device globals -- no allocation allowed)
__device__ float g_xa[M_SEQ*EE];
__device__ float g_xb[M_SEQ*HH];
__device__ float g_xg[M_SEQ*G4];
__device__ float g_encp[NB*TI*JJ];
__device__ float g_decp[M_SEQ*JJ];
__device__ float g_h[3][2][NB*HH];
__device__ unsigned g_bar;
__device__ unsigned g_T[M_OUT*256];    // fp16 tanh(enc+dec), fragment-packed (136 MB)
__device__ unsigned g_bw[VV*256];      // fp16 out_w, fragment-packed (1 MB)

// ---------------------------------------------------------------------------
__global__ void k_embed(const int* __restrict__ tgt, const float* __restrict__ emb,
                        float* __restrict__ x) {
    int idx = blockIdx.x*blockDim.x + threadIdx.x;
    if (idx == 0) g_bar = 0u;
    if (idx >= M_SEQ*EE) return;
    int e = idx & (EE-1);
    int m = idx >> 9;
    int n = m / TO1, t = m - n*TO1;
    int tok = (t == 0) ? 0 : tgt[n*TO + t - 1];
    x[idx] = emb[tok*EE + e];
}

// ---------------------------------------------------------------------------
// C[m,n] = sum_k A[m,k]*B[n,k] + b1[n] + b2[n], register-prefetch double-buffer
// ---------------------------------------------------------------------------
__global__ void k_gemm_abT(const float* __restrict__ A, const float* __restrict__ B,
                           const float* __restrict__ b1, const float* __restrict__ b2,
                           float* __restrict__ C, int M, int Nn, int K) {
    __shared__ float As[16][64];
    __shared__ float Bs[16][64];
    const int tid = threadIdx.x;
    const int m0 = blockIdx.x*64, n0 = blockIdx.y*64;
    const int lr = tid >> 2;
    const int lk = (tid & 3) << 2;
    const int tx = tid & 15, ty = tid >> 4;
    float acc[4][4] = {};
    const bool mval = (m0 + lr) < M;
    const float* Ap = A + (size_t)(m0+lr)*K + lk;
    const float* Bp = B + (size_t)(n0+lr)*K + lk;

    float4 av = make_float4(0.f,0.f,0.f,0.f);
    if (mval) av = *(const float4*)(Ap);
    float4 bv = *(const float4*)(Bp);

    for (int k0 = 0; k0 < K; k0 += 16) {
        As[lk+0][lr]=av.x; As[lk+1][lr]=av.y; As[lk+2][lr]=av.z; As[lk+3][lr]=av.w;
        Bs[lk+0][lr]=bv.x; Bs[lk+1][lr]=bv.y; Bs[lk+2][lr]=bv.z; Bs[lk+3][lr]=bv.w;
        __syncthreads();
        float4 av2 = make_float4(0.f,0.f,0.f,0.f);
        float4 bv2 = make_float4(0.f,0.f,0.f,0.f);
        if (k0 + 16 < K) {
            if (mval) av2 = *(const float4*)(Ap + k0 + 16);
            bv2 = *(const float4*)(Bp + k0 + 16);
        }
#pragma unroll
        for (int k = 0; k < 16; k++) {
            float4 a4 = *(const float4*)&As[k][ty*4];
            float4 b4 = *(const float4*)&Bs[k][tx*4];
            float aa[4] = {a4.x,a4.y,a4.z,a4.w};
            float bb[4] = {b4.x,b4.y,b4.z,b4.w};
#pragma unroll
            for (int i=0;i<4;i++)
#pragma unroll
                for (int j=0;j<4;j++) acc[i][j] += aa[i]*bb[j];
        }
        __syncthreads();
        av = av2; bv = bv2;
    }
    float bias[4];
#pragma unroll
    for (int j=0;j<4;j++) {
        int nn = n0 + tx*4 + j;
        bias[j] = (b1 ? b1[nn] : 0.f) + (b2 ? b2[nn] : 0.f);
    }
#pragma unroll
    for (int i=0;i<4;i++) {
        int m = m0 + ty*4 + i;
        if (m < M) {
            float4 o = make_float4(acc[i][0]+bias[0], acc[i][1]+bias[1],
                                   acc[i][2]+bias[2], acc[i][3]+bias[3]);
            *(float4*)&C[(size_t)m*Nn + n0 + tx*4] = o;
        }
    }
}

// ---------------------------------------------------------------------------
// Persistent wavefront LSTM; Whh in SMEM; packed f32x2 FMA; round-12 global
// release/acquire barrier with nanosleep backoff (proven best).
// ---------------------------------------------------------------------------
__device__ __forceinline__ float sigf(float x) { return 1.f/(1.f + expf(-x)); }

__device__ __forceinline__ void fma2(unsigned long long& acc,
                                     unsigned long long a, unsigned long long b) {
    asm("fma.rn.f32x2 %0, %1, %2, %0;" : "+l"(acc) : "l"(a), "l"(b));
}

__device__ __forceinline__ void dot8x2(const float* Wrow0, const float* sh,
                                       int lane, int wstride,
                                       unsigned long long acc2[8][4]) {
#pragma unroll
    for (int it = 0; it < 4; it++) {
        const int kv4 = (it*32 + lane) * 4;
        ulonglong2 H0 = *(const ulonglong2*)&sh[0*HH + kv4];
        ulonglong2 H1 = *(const ulonglong2*)&sh[1*HH + kv4];
        ulonglong2 H2 = *(const ulonglong2*)&sh[2*HH + kv4];
        ulonglong2 H3 = *(const ulonglong2*)&sh[3*HH + kv4];
#pragma unroll
        for (int r = 0; r < 8; r++) {
            ulonglong2 W = *(const ulonglong2*)(Wrow0 + r*wstride + kv4);
            fma2(acc2[r][0], W.x, H0.x); fma2(acc2[r][0], W.y, H0.y);
            fma2(acc2[r][1], W.x, H1.x); fma2(acc2[r][1], W.y, H1.y);
            fma2(acc2[r][2], W.x, H2.x); fma2(acc2[r][2], W.y, H2.y);
            fma2(acc2[r][3], W.x, H3.x); fma2(acc2[r][3], W.y, H3.y);
        }
    }
}

__device__ __forceinline__ float unpk(unsigned long long v) {
    return __uint_as_float((unsigned)(v & 0xffffffffu)) +
           __uint_as_float((unsigned)(v >> 32));
}

__global__ void __launch_bounds__(256, 1) k_lstm_wave(
    const float* __restrict__ xg0,
    const float* __restrict__ Whh0,
    const float* __restrict__ Wih1, const float* __restrict__ Whh1,
    const float* __restrict__ bih1, const float* __restrict__ bhh1,
    const float* __restrict__ Wih2, const float* __restrict__ Whh2,
    const float* __restrict__ bih2, const float* __restrict__ bhh2,
    float* __restrict__ out_seq)
{
    extern __shared__ float Wsm[];       // [64][512] fp32 Whh slice
    const int layer = blockIdx.x >> 5;
    const int blk   = blockIdx.x & 31;
    const int j0    = blk * 16;
    const int tid   = threadIdx.x, warp = tid >> 5, lane = tid & 31;

    const float* Whh = (layer==0) ? Whh0 : (layer==1 ? Whh1 : Whh2);
    const float* Wih = (layer==1) ? Wih1 : Wih2;
    const float* bi  = (layer==1) ? bih1 : bih2;
    const float* bh  = (layer==1) ? bhh1 : bhh2;

    __shared__ __align__(16) float sh[NB*HH];
    __shared__ __align__(16) float si[NB*HH];
    __shared__ float gsm[4][NB][16];

    // Preload this block's Whh slice: local row = q*16 + jj  (q=gate)
    for (int i = tid; i < 64*512/4; i += 256) {
        int row = i >> 7;
        int k   = (i << 2) & 511;
        int q = row >> 4, jj = row & 15;
        ((float4*)Wsm)[i] = *(const float4*)&Whh[(size_t)(q*HH + j0 + jj)*HH + k];
    }

    const int rl0 = warp*8;
    const int q   = rl0 >> 4;
    const int jb  = rl0 & 15;
    const float* WsmR = Wsm + rl0*512;
    const float* WihR = Wih + (size_t)(q*HH + j0 + jb)*HH;

    const int eb = tid >> 4, ejj = tid & 15, ej = j0 + ejj;
    float c_reg = 0.f;
    float bias_q[4] = {0.f, 0.f, 0.f, 0.f};
    if (tid < 64 && layer > 0) {
#pragma unroll
        for (int qq = 0; qq < 4; qq++) bias_q[qq] = bi[qq*HH + ej] + bh[qq*HH + ej];
    }
    __syncthreads();                     // Wsm ready

    unsigned* barp = &g_bar;

    for (int tick = 0; tick < NTICK; tick++) {
        const int t = tick - layer;
        if (t >= 0 && t < TO1) {
            const int rp = (tick + 1) & 1;
            const bool havePrev = (t > 0);
            if (havePrev) {
                const float* hp = g_h[layer][rp];
                for (int i = tid; i < NB*HH; i += 256) sh[i] = __ldcg(hp + i);
            }
            if (layer > 0) {
                const float* hi = g_h[layer-1][rp];
                for (int i = tid; i < NB*HH; i += 256) si[i] = __ldcg(hi + i);
            }
            __syncthreads();

            unsigned long long acc2[8][4] = {};
            if (havePrev) dot8x2(WsmR, sh, lane, 512, acc2);
            if (layer > 0) dot8x2(WihR, si, lane, HH, acc2);

            float acc[8][4];
#pragma unroll
            for (int r = 0; r < 8; r++)
#pragma unroll
                for (int b = 0; b < 4; b++) acc[r][b] = unpk(acc2[r][b]);
#pragma unroll
            for (int r = 0; r < 8; r++) {
#pragma unroll
                for (int off = 16; off; off >>= 1) {
                    acc[r][0] += __shfl_down_sync(0xffffffffu, acc[r][0], off);
                    acc[r][1] += __shfl_down_sync(0xffffffffu, acc[r][1], off);
                    acc[r][2] += __shfl_down_sync(0xffffffffu, acc[r][2], off);
                    acc[r][3] += __shfl_down_sync(0xffffffffu, acc[r][3], off);
                }
            }
            if (lane == 0) {
#pragma unroll
                for (int r = 0; r < 8; r++) {
                    gsm[q][0][jb+r] = acc[r][0];
                    gsm[q][1][jb+r] = acc[r][1];
                    gsm[q][2][jb+r] = acc[r][2];
                    gsm[q][3][jb+r] = acc[r][3];
                }
            }
            __syncthreads();
            if (tid < 64) {
                float p[4];
                if (layer == 0) {
                    const float* xp = xg0 + (size_t)(eb*TO1 + t)*G4;
#pragma unroll
                    for (int qq = 0; qq < 4; qq++) p[qq] = gsm[qq][eb][ejj] + xp[qq*HH + ej];
                } else {
#pragma unroll
                    for (int qq = 0; qq < 4; qq++) p[qq] = gsm[qq][eb][ejj] + bias_q[qq];
                }
                float iv = sigf(p[0]), fv = sigf(p[1]), gv = tanhf(p[2]), ov = sigf(p[3]);
                c_reg = fv*c_reg + iv*gv;
                float h = ov * tanhf(c_reg);
                g_h[layer][tick & 1][eb*HH + ej] = h;
                if (layer == 2) out_seq[(size_t)(eb*TO1 + t)*HH + ej] = h;
            }
        }
        // ---- release/acquire global barrier (round-12 proven config) ----
        __syncthreads();
        if (tid == 0) {
            asm volatile("red.release.gpu.global.add.u32 [%0], %1;"
                         :: "l"(barp), "r"(1u) : "memory");
            const unsigned target = (unsigned)gridDim.x * (unsigned)(tick + 1);
            unsigned v;
            while (true) {
                asm volatile("ld.acquire.gpu.global.u32 %0, [%1];"
                             : "=r"(v) : "l"(barp) : "memory");
                if (v >= target) break;
                __nanosleep(64);
            }
        }
        __syncthreads();
    }
}

// ---------------------------------------------------------------------------
// T = fp16(tanh(encp+decp)) in m16n8k16 A-fragment order (fast HW tanh).
// ---------------------------------------------------------------------------
__device__ __forceinline__ float tanh_fast(float x) {
    float y;
    asm("tanh.approx.f32 %0, %1;" : "=f"(y) : "f"(x));
    return y;
}

__device__ __forceinline__ void row_ptrs(int m, const float* __restrict__ encp,
                                         const float* __restrict__ decp,
                                         const float*& ep, const float*& dp) {
    const int n   = m / (TI*TO1);
    const int rem = m - n*(TI*TO1);
    const int t   = rem / TO1;
    const int u   = rem - t*TO1;
    ep = encp + (size_t)(n*TI + t)*JJ;
    dp = decp + (size_t)(n*TO1 + u)*JJ;
}

__global__ void k_tanh(const float* __restrict__ encp, const float* __restrict__ decp,
                       uint4* __restrict__ T) {
    const int idx   = blockIdx.x*256 + threadIdx.x;
    const int lane  = idx & 31;
    const int ks    = (idx >> 5) & 31;
    const int mtile = idx >> 10;
    const int g = lane >> 2, tg = lane & 3;
    const int k0 = ks*16 + 2*tg;

    const float *eA, *dA, *eB, *dB;
    row_ptrs(mtile*16 + g,     encp, decp, eA, dA);
    row_ptrs(mtile*16 + g + 8, encp, decp, eB, dB);

    float2 ea0 = *(const float2*)(eA + k0), ea1 = *(const float2*)(eA + k0 + 8);
    float2 da0 = *(const float2*)(dA + k0), da1 = *(const float2*)(dA + k0 + 8);
    float2 eb0 = *(const float2*)(eB + k0), eb1 = *(const float2*)(eB + k0 + 8);
    float2 db0 = *(const float2*)(dB + k0), db1 = *(const float2*)(dB + k0 + 8);

    __half2 a0 = __floats2half2_rn(tanh_fast(ea0.x+da0.x), tanh_fast(ea0.y+da0.y));
    __half2 a1 = __floats2half2_rn(tanh_fast(eb0.x+db0.x), tanh_fast(eb0.y+db0.y));
    __half2 a2 = __floats2half2_rn(tanh_fast(ea1.x+da1.x), tanh_fast(ea1.y+da1.y));
    __half2 a3 = __floats2half2_rn(tanh_fast(eb1.x+db1.x), tanh_fast(eb1.y+db1.y));
    uint4 o;
    o.x = *(unsigned*)&a0; o.y = *(unsigned*)&a1;
    o.z = *(unsigned*)&a2; o.w = *(unsigned*)&a3;
    T[idx] = o;
}

// out_w -> fp16 in B-fragment order
__global__ void k_cvtB(const float* __restrict__ w, uint2* __restrict__ o) {
    const int idx   = blockIdx.x*256 + threadIdx.x;
    const int lane  = idx & 31;
    const int ks    = (idx >> 5) & 31;
    const int vtile = idx >> 10;
    const int g = lane >> 2, tg = lane & 3;
    const int k0 = ks*16 + 2*tg;
    const float* wp = w + (size_t)(vtile*8 + g)*JJ;
    float2 f0 = *(const float2*)(wp + k0);
    float2 f1 = *(const float2*)(wp + k0 + 8);
    __half2 b0 = __floats2half2_rn(f0.x, f0.y);
    __half2 b1 = __floats2half2_rn(f1.x, f1.y);
    uint2 v;
    v.x = *(unsigned*)&b0; v.y = *(unsigned*)&b1;
    o[idx] = v;
}

// ---------------------------------------------------------------------------
// SMEM-free fp16 HMMA GEMM with explicit 2-deep register double-buffering.
// ---------------------------------------------------------------------------
__device__ __forceinline__ void mma16816(float d[4], const unsigned a[4],
                                         const unsigned b[2]) {
    asm volatile(
        "mma.sync.aligned.m16n8k16.row.col.f32.f16.f16.f32 "
        "{%0,%1,%2,%3}, {%4,%5,%6,%7}, {%8,%9}, {%0,%1,%2,%3};"
        : "+f"(d[0]), "+f"(d[1]), "+f"(d[2]), "+f"(d[3])
        : "r"(a[0]), "r"(a[1]), "r"(a[2]), "r"(a[3]), "r"(b[0]), "r"(b[1]));
}

__global__ void __launch_bounds__(256) k_mma_out(
    const uint4* __restrict__ Tf, const uint2* __restrict__ Bf,
    float* __restrict__ out)
{
    const int tid = threadIdx.x;
    const int w = tid >> 5, lane = tid & 31;
    const int wm = w >> 2, wn = w & 3;
    const int m0 = blockIdx.x * 128;
    const int v0 = blockIdx.y * 256;

    const uint4* Ap[4];
#pragma unroll
    for (int mt = 0; mt < 4; mt++)
        Ap[mt] = Tf + ((size_t)(blockIdx.x*8 + wm*4 + mt) * 32) * 32 + lane;
    const uint2* Bp[8];
#pragma unroll
    for (int nt = 0; nt < 8; nt++)
        Bp[nt] = Bf + ((size_t)(blockIdx.y*32 + wn*8 + nt) * 32) * 32 + lane;

    float d[4][8][4];
#pragma unroll
    for (int i = 0; i < 4; i++)
#pragma unroll
        for (int j = 0; j < 8; j++)
#pragma unroll
            for (int k = 0; k < 4; k++) d[i][j][k] = 0.f;

    unsigned a[2][4][4], b[2][8][2];
#pragma unroll
    for (int mt = 0; mt < 4; mt++) {
        uint4 v = Ap[mt][0];
        a[0][mt][0] = v.x; a[0][mt][1] = v.y; a[0][mt][2] = v.z; a[0][mt][3] = v.w;
    }
#pragma unroll
    for (int nt = 0; nt < 8; nt++) {
        uint2 v = Bp[nt][0];
        b[0][nt][0] = v.x; b[0][nt][1] = v.y;
    }

#pragma unroll 2
    for (int ks = 0; ks < 32; ks++) {
        const int cur = ks & 1, nxt = cur ^ 1;
        if (ks < 31) {
#pragma unroll
            for (int mt = 0; mt < 4; mt++) {
                uint4 v = Ap[mt][(ks+1)*32];
                a[nxt][mt][0] = v.x; a[nxt][mt][1] = v.y;
                a[nxt][mt][2] = v.z; a[nxt][mt][3] = v.w;
            }
#pragma unroll
            for (int nt = 0; nt < 8; nt++) {
                uint2 v = Bp[nt][(ks+1)*32];
                b[nxt][nt][0] = v.x; b[nxt][nt][1] = v.y;
            }
        }
#pragma unroll
        for (int mt = 0; mt < 4; mt++)
#pragma unroll
            for (int nt = 0; nt < 8; nt++)
                mma16816(d[mt][nt], a[cur][mt], b[cur][nt]);
    }

    const int g = lane >> 2, tg = lane & 3;
#pragma unroll
    for (int mt = 0; mt < 4; mt++) {
        const int row = m0 + wm*64 + mt*16 + g;
#pragma unroll
        for (int nt = 0; nt < 8; nt++) {
            const int col = v0 + wn*64 + nt*8 + 2*tg;
            *(float2*)(out + (size_t)row*VV + col) =
                make_float2(d[mt][nt][0], d[mt][nt][1]);
            *(float2*)(out + (size_t)(row + 8)*VV + col) =
                make_float2(d[mt][nt][2], d[mt][nt][3]);
        }
    }
}

// ---------------------------------------------------------------------------
extern "C" void kernel_launch(void* const* d_in, const int* in_sizes, int n_in,
                              void* d_out, int out_size) {
    const float* enc_out = (const float*)d_in[0];
    const int*   tgt     = (const int*)  d_in[1];
    const float* emb     = (const float*)d_in[2];
    const float* Wih0    = (const float*)d_in[3];
    const float* Whh0    = (const float*)d_in[4];
    const float* bih0    = (const float*)d_in[5];
    const float* bhh0    = (const float*)d_in[6];
    const float* Wih1    = (const float*)d_in[7];
    const float* Whh1    = (const float*)d_in[8];
    const float* bih1    = (const float*)d_in[9];
    const float* bhh1    = (const float*)d_in[10];
    const float* Wih2    = (const float*)d_in[11];
    const float* Whh2    = (const float*)d_in[12];
    const float* bih2    = (const float*)d_in[13];
    const float* bhh2    = (const float*)d_in[14];
    const float* enc_w   = (const float*)d_in[15];
    const float* dec_w   = (const float*)d_in[16];
    const float* dec_b   = (const float*)d_in[17];
    const float* out_w   = (const float*)d_in[18];
    float* out = (float*)d_out;

    float *xa, *xb, *xg, *encp, *decp;
    unsigned *Tb, *Bw;
    cudaGetSymbolAddress((void**)&xa,   g_xa);
    cudaGetSymbolAddress((void**)&xb,   g_xb);
    cudaGetSymbolAddress((void**)&xg,   g_xg);
    cudaGetSymbolAddress((void**)&encp, g_encp);
    cudaGetSymbolAddress((void**)&decp, g_decp);
    cudaGetSymbolAddress((void**)&Tb,   g_T);
    cudaGetSymbolAddress((void**)&Bw,   g_bw);

    cudaFuncSetAttribute(k_lstm_wave, cudaFuncAttributeMaxDynamicSharedMemorySize,
                         WSM_BYTES);

    // side stream + fork/join events (created once; capture-legal fork pattern)
    static cudaStream_t s2 = nullptr;
    static cudaEvent_t evF = nullptr, evJ = nullptr;
    if (!s2) {
        cudaStreamCreateWithFlags(&s2, cudaStreamNonBlocking);
        cudaEventCreateWithFlags(&evF, cudaEventDisableTiming);
        cudaEventCreateWithFlags(&evJ, cudaEventDisableTiming);
    }

    // fork: enc_p projection + out_w conversion run concurrently with LSTM chain
    cudaEventRecord(evF, 0);
    cudaStreamWaitEvent(s2, evF, 0);
    {
        dim3 g((NB*TI)/64, JJ/64);
        k_gemm_abT<<<g, 256, 0, s2>>>(enc_out, enc_w, nullptr, nullptr, encp,
                                      NB*TI, JJ, 512);
    }
    k_cvtB<<<(VV/8)*32*32/256, 256, 0, s2>>>(out_w, (uint2*)Bw);
    cudaEventRecord(evJ, s2);

    // main stream chain
    k_embed<<<(M_SEQ*EE + 255)/256, 256>>>(tgt, emb, xa);
    {
        dim3 g((M_SEQ + 63)/64, G4/64);
        k_gemm_abT<<<g, 256>>>(xa, Wih0, bih0, bhh0, xg, M_SEQ, G4, HH);
    }
    k_lstm_wave<<<GRID_LSTM, 256, WSM_BYTES>>>(xg, Whh0,
                                    Wih1, Whh1, bih1, bhh1,
                                    Wih2, Whh2, bih2, bhh2, xb);
    {
        dim3 g((M_SEQ + 63)/64, JJ/64);
        k_gemm_abT<<<g, 256>>>(xb, dec_w, dec_b, nullptr, decp, M_SEQ, JJ, HH);
    }

    // join: tanh needs encp (s2); mma additionally needs Bw (s2)
    cudaStreamWaitEvent(0, evJ, 0);
    k_tanh<<<(M_OUT/16)*32*32/256, 256>>>(encp, decp, (uint4*)Tb);

    {
        dim3 g(M_OUT/128, VV/256);
        k_mma_out<<<g, 256>>>((const uint4*)Tb, (const uint2*)Bw, out);
    }
}